// round 10
// baseline (speedup 1.0000x reference)
#include <cuda_runtime.h>
#include <math_constants.h>

#define SEQ    2048
#define DM     1024
#define NH     16
#define DH     64
#define BH     64
#define MR     8192
#define KDIM   1024
#define GRIDC  296

__device__ float g_q[(size_t)BH*SEQ*DH];
__device__ float g_k[(size_t)BH*SEQ*DH];
__device__ float g_v[(size_t)BH*DH*SEQ];     // TRANSPOSED: [bh][d][pos]
__device__ float g_attn[(size_t)MR*DM];
__device__ float g_x[(size_t)MR*DM];
__device__ float g_wqkv[(size_t)3*DM*DM];    // TRANSPOSED: [n][k]
__device__ float g_wout[(size_t)DM*DM];      // TRANSPOSED: [n][k]

__device__ __forceinline__ unsigned cvt_tf32(float f){
    unsigned u; asm("cvt.rna.tf32.f32 %0, %1;" : "=r"(u) : "f"(f)); return u;
}
__device__ __forceinline__ float tf32f(float f){ return __uint_as_float(cvt_tf32(f)); }

__device__ __forceinline__ void mma8(float4& d, unsigned a0, unsigned a1, unsigned a2,
                                     unsigned a3, unsigned b0, unsigned b1){
    asm volatile(
      "mma.sync.aligned.m16n8k8.row.col.f32.tf32.tf32.f32 "
      "{%0,%1,%2,%3},{%4,%5,%6,%7},{%8,%9},{%0,%1,%2,%3};"
      : "+f"(d.x), "+f"(d.y), "+f"(d.z), "+f"(d.w)
      : "r"(a0), "r"(a1), "r"(a2), "r"(a3), "r"(b0), "r"(b1));
}
__device__ __forceinline__ void ldsm4(unsigned* r, unsigned addr){
    asm volatile("ldmatrix.sync.aligned.m8n8.x4.shared.b16 {%0,%1,%2,%3}, [%4];"
        : "=r"(r[0]), "=r"(r[1]), "=r"(r[2]), "=r"(r[3]) : "r"(addr));
}
__device__ __forceinline__ void cpasync16(void* smem, const void* g){
    unsigned s = (unsigned)__cvta_generic_to_shared(smem);
    asm volatile("cp.async.cg.shared.global [%0], [%1], 16;" :: "r"(s), "l"(g));
}
__device__ __forceinline__ void cp_commit(){ asm volatile("cp.async.commit_group;"); }
template<int N> __device__ __forceinline__ void cp_wait(){
    asm volatile("cp.async.wait_group %0;" :: "n"(N));
}
__device__ __forceinline__ int swz(int r, int c){
    return r * 64 + ((((c >> 2) ^ (r & 7))) << 2) + (c & 3);
}

// ---------------- input passes ----------------
__global__ void round_x(const float4* __restrict__ in, int n4){
    int i = blockIdx.x * blockDim.x + threadIdx.x;
    if (i < n4){
        float4 v = in[i];
        v.x = tf32f(v.x); v.y = tf32f(v.y); v.z = tf32f(v.z); v.w = tf32f(v.w);
        ((float4*)g_x)[i] = v;
    }
}
// both weights in one launch: bx<96 -> w_qkv (N=3072), else w_out (N=1024)
__global__ void transpose_w(const float* __restrict__ wq, const float* __restrict__ wo){
    __shared__ float tile[32][33];
    int bx = blockIdx.x;
    const float* in = (bx < 96) ? wq : wo;
    float* out      = (bx < 96) ? g_wqkv : g_wout;
    int N           = (bx < 96) ? 3072 : 1024;
    int n0 = ((bx < 96) ? bx : bx - 96) * 32, k0 = blockIdx.y * 32;
    int tx = threadIdx.x, ty = threadIdx.y;
    #pragma unroll
    for (int i = 0; i < 32; i += 8)
        tile[ty + i][tx] = in[(size_t)(k0 + ty + i) * N + n0 + tx];
    __syncthreads();
    #pragma unroll
    for (int i = 0; i < 32; i += 8)
        out[(size_t)(n0 + ty + i) * KDIM + k0 + tx] = tf32f(tile[tx][ty + i]);
}

// ------- persistent GEMM: 128x128x32 tiles, cross-tile chunk pipeline ------
#define GSTG 8192
#define GSMEM_BYTES (3 * GSTG * 4)

__global__ __launch_bounds__(256, 2) void gemm_tc(const float* __restrict__ bias,
                                                  float* __restrict__ C, int mode,
                                                  int ntiles, int ntn)
{
    extern __shared__ float sm[];
    const float* __restrict__ A = (mode == 0) ? g_x    : g_attn;
    const float* __restrict__ B = (mode == 0) ? g_wqkv : g_wout;

    const int bid = blockIdx.x;
    const int nloc = (bid < ntiles) ? ((ntiles - 1 - bid) / GRIDC + 1) : 0;
    if (nloc == 0) return;
    const int nchunks = nloc * 32;

    const int t = threadIdx.x, lane = t & 31, w = t >> 5;
    const int g = lane >> 2, j = lane & 3;
    const int wm = w >> 2, wn = w & 3;

    const int til = lane >> 3, rin = lane & 7;
    const int lrow = (til & 1) * 8 + rin;
    const int lc4o = til >> 1;
    const unsigned smu = (unsigned)__cvta_generic_to_shared(sm);

    const int ldr = t >> 3, ldc = t & 7;
    auto issue = [&](int chunk, int slot){
        if (chunk >= nchunks) return;
        const int gt = bid + (chunk >> 5) * GRIDC;
        const int m0 = (gt / ntn) << 7, n0 = (gt % ntn) << 7;
        const int kt = chunk & 31;
        float* dA = sm + slot * GSTG;
        float* dB = dA + 4096;
        const float* sA = A + (size_t)(m0 + ldr) * KDIM + kt * 32 + ldc * 4;
        const float* sB = B + (size_t)(n0 + ldr) * KDIM + kt * 32 + ldc * 4;
        #pragma unroll
        for (int i = 0; i < 4; i++){
            int rr = ldr + 32 * i;
            int off = rr * 32 + ((ldc ^ (rr & 7)) << 2);
            cpasync16(dA + off, sA + (size_t)32 * i * KDIM);
            cpasync16(dB + off, sB + (size_t)32 * i * KDIM);
        }
    };

    float4 acc[4][4];
    #pragma unroll
    for (int i = 0; i < 4; i++)
        #pragma unroll
        for (int n = 0; n < 4; n++) acc[i][n] = make_float4(0.f, 0.f, 0.f, 0.f);

    issue(0, 0); cp_commit();
    issue(1, 1); cp_commit();
    cp_wait<1>();

    for (int c = 0; c < nchunks; c++){
        __syncthreads();
        issue(c + 2, (c + 2) % 3); cp_commit();

        const unsigned as0 = smu + (c % 3) * GSTG * 4;
        const unsigned bs0 = as0 + 4096 * 4;
        #pragma unroll
        for (int ks = 0; ks < 4; ks++){
            const unsigned cof = (unsigned)((ks * 2 + lc4o) ^ rin) << 4;
            unsigned a[4][4];
            #pragma unroll
            for (int mt = 0; mt < 4; mt++)
                ldsm4(a[mt], as0 + (unsigned)(wm * 64 + mt * 16 + lrow) * 128 + cof);
            unsigned bf[2][4];
            #pragma unroll
            for (int np = 0; np < 2; np++)
                ldsm4(bf[np], bs0 + (unsigned)(wn * 32 + np * 16 + lrow) * 128 + cof);
            #pragma unroll
            for (int mt = 0; mt < 4; mt++)
                #pragma unroll
                for (int nt = 0; nt < 4; nt++)
                    mma8(acc[mt][nt], a[mt][0], a[mt][1], a[mt][2], a[mt][3],
                         bf[nt >> 1][nt & 1], bf[nt >> 1][2 + (nt & 1)]);
        }

        if ((c & 31) == 31){
            const int gt = bid + (c >> 5) * GRIDC;
            const int m0 = (gt / ntn) << 7, n0 = (gt % ntn) << 7;
            #pragma unroll
            for (int mt = 0; mt < 4; mt++){
                const int r = m0 + wm * 64 + mt * 16 + g;
                #pragma unroll
                for (int nt = 0; nt < 4; nt++){
                    const int f = n0 + wn * 32 + nt * 8 + (j << 1);
                    float2 bb = *(const float2*)&bias[f];
                    float4 a = acc[mt][nt];
                    if (mode == 0){
                        int qk = f >> 10, h = (f >> 6) & 15, dd = f & 63;
                        int b_i = r >> 11, pos = r & 2047;
                        int bhh = b_i * NH + h;
                        if (qk == 2){
                            float* vb = g_v + ((size_t)bhh * DH + dd) * SEQ + pos;
                            vb[0]       = tf32f(a.x + bb.x);
                            vb[SEQ]     = tf32f(a.y + bb.y);
                            vb[8]       = tf32f(a.z + bb.x);
                            vb[SEQ + 8] = tf32f(a.w + bb.y);
                        } else {
                            float* dst = (qk == 0) ? g_q : g_k;
                            size_t base = ((size_t)bhh * SEQ + pos) * DH + dd;
                            *(float2*)&dst[base] =
                                make_float2(tf32f(a.x + bb.x), tf32f(a.y + bb.y));
                            *(float2*)&dst[base + 8 * DH] =
                                make_float2(tf32f(a.z + bb.x), tf32f(a.w + bb.y));
                        }
                    } else {
                        size_t off = (size_t)r * DM + f;
                        *(float2*)&C[off]          = make_float2(a.x + bb.x, a.y + bb.y);
                        *(float2*)&C[off + 8 * DM] = make_float2(a.z + bb.x, a.w + bb.y);
                    }
                    acc[mt][nt] = make_float4(0.f, 0.f, 0.f, 0.f);
                }
            }
        }
        cp_wait<1>();
    }
}

// ---------------- causal attention (R9) -------------------------------------
#define AT_SMEM_BYTES (24576 * 4)
__global__ __launch_bounds__(256, 2) void attn_tc()
{
    extern __shared__ float sm[];
    const unsigned smu = (unsigned)__cvta_generic_to_shared(sm);

    const int qt = gridDim.x - 1 - blockIdx.x;
    const int bh = blockIdx.y;
    const int t = threadIdx.x, lane = t & 31, w = t >> 5;
    const int g = lane >> 2, j = lane & 3;

    const int til = lane >> 3, rin = lane & 7;
    const int lrow = (til & 1) * 8 + rin;
    const int lc4o = til >> 1;

    const float* qg = g_q + ((size_t)bh * SEQ + qt * 128) * DH;
    const float* kg = g_k + (size_t)bh * SEQ * DH;
    const float* vg = g_v + (size_t)bh * DH * SEQ;

    const int lr = t >> 4, lc4 = t & 15;
    auto issueKV = [&](int kt, int slot){
        const float* ksrc = kg + (size_t)kt * 64 * DH;
        float* kd = sm + slot * 8192;
        float* vd = kd + 4096;
        #pragma unroll
        for (int i = 0; i < 4; i++){
            int r = lr + 16 * i;
            int off = r * 64 + ((lc4 ^ (r & 7)) << 2);
            cpasync16(kd + off, ksrc + r * 64 + lc4 * 4);
            cpasync16(vd + off, vg + (size_t)r * SEQ + kt * 64 + lc4 * 4);
        }
    };

    {
        float* qd = sm + 2 * 8192;
        #pragma unroll
        for (int i = 0; i < 8; i++){
            int r = lr + 16 * i;
            cpasync16(qd + swz(r, lc4 * 4), qg + (size_t)r * 64 + lc4 * 4);
        }
    }
    cp_commit();
    issueKV(0, 0); cp_commit();
    issueKV(1, 1); cp_commit();
    cp_wait<2>();
    __syncthreads();

    unsigned qa[8][4];
    {
        unsigned rb = 2u * 8192u * 4u + (unsigned)(w * 16 + lrow) * 256u;
        #pragma unroll
        for (int ks = 0; ks < 8; ks++){
            unsigned c4 = (unsigned)((ks * 2 + lc4o) ^ rin) << 4;
            ldsm4(qa[ks], smu + rb + c4);
        }
    }
    __syncthreads();
    cp_wait<1>();

    float4 oacc[8];
    #pragma unroll
    for (int i = 0; i < 8; i++) oacc[i] = make_float4(0.f, 0.f, 0.f, 0.f);
    float lp0 = 0.f, lp1 = 0.f;

    const int srcA = (g << 2) + (j >> 1);
    const int srcB = srcA + 2;
    const bool odd = (j & 1);
    const int rq0 = qt * 128 + w * 16 + g;

    const int ktmax = 2 * qt + 1;
    for (int kt = 0; kt <= ktmax; kt++){
        __syncthreads();
        if (kt + 2 <= ktmax){ issueKV(kt + 2, (kt + 2) % 3); cp_commit(); }

        const unsigned kB = smu + (unsigned)((kt % 3) * 8192 * 4);
        const unsigned vB = kB + 4096u * 4u;

        float4 p[8];
        #pragma unroll
        for (int i = 0; i < 8; i++) p[i] = make_float4(0.f, 0.f, 0.f, 0.f);
        #pragma unroll
        for (int ks = 0; ks < 8; ks++){
            unsigned c4 = (unsigned)((ks * 2 + lc4o) ^ rin) << 4;
            unsigned kb[4][4];
            #pragma unroll
            for (int pp = 0; pp < 4; pp++)
                ldsm4(kb[pp], kB + (unsigned)(pp * 16 + lrow) * 256u + c4);
            #pragma unroll
            for (int pp = 0; pp < 4; pp++){
                mma8(p[2*pp],   qa[ks][0], qa[ks][1], qa[ks][2], qa[ks][3], kb[pp][0], kb[pp][2]);
                mma8(p[2*pp+1], qa[ks][0], qa[ks][1], qa[ks][2], qa[ks][3], kb[pp][1], kb[pp][3]);
            }
        }

        const bool diag = (kt >= 2 * qt);
        #pragma unroll
        for (int nt = 0; nt < 8; nt++){
            int ck = kt * 64 + nt * 8 + (j << 1);
            float4 s = p[nt];
            s.x *= 0.125f; s.y *= 0.125f; s.z *= 0.125f; s.w *= 0.125f;
            if (diag){
                if (ck     > rq0)     s.x = -CUDART_INF_F;
                if (ck + 1 > rq0)     s.y = -CUDART_INF_F;
                if (ck     > rq0 + 8) s.z = -CUDART_INF_F;
                if (ck + 1 > rq0 + 8) s.w = -CUDART_INF_F;
            }
            s.x = tf32f(__expf(s.x)); s.y = tf32f(__expf(s.y));
            s.z = tf32f(__expf(s.z)); s.w = tf32f(__expf(s.w));
            lp0 += s.x + s.y;
            lp1 += s.z + s.w;
            p[nt] = s;
        }

        #pragma unroll
        for (int nt = 0; nt < 8; nt++){
            float4 v = p[nt];
            float ax = __shfl_sync(0xffffffffu, v.x, srcA);
            float ay = __shfl_sync(0xffffffffu, v.y, srcA);
            float az = __shfl_sync(0xffffffffu, v.z, srcA);
            float aw = __shfl_sync(0xffffffffu, v.w, srcA);
            float bx = __shfl_sync(0xffffffffu, v.x, srcB);
            float by = __shfl_sync(0xffffffffu, v.y, srcB);
            float bz = __shfl_sync(0xffffffffu, v.z, srcB);
            float bw = __shfl_sync(0xffffffffu, v.w, srcB);
            unsigned pa0 = __float_as_uint(odd ? ay : ax);
            unsigned pa1 = __float_as_uint(odd ? aw : az);
            unsigned pa2 = __float_as_uint(odd ? by : bx);
            unsigned pa3 = __float_as_uint(odd ? bw : bz);

            unsigned c4 = (unsigned)((nt * 2 + lc4o) ^ rin) << 4;
            unsigned vf[4][4];
            #pragma unroll
            for (int pp = 0; pp < 4; pp++)
                ldsm4(vf[pp], vB + (unsigned)(pp * 16 + lrow) * 256u + c4);
            #pragma unroll
            for (int pp = 0; pp < 4; pp++){
                mma8(oacc[2*pp],   pa0, pa1, pa2, pa3, vf[pp][0], vf[pp][2]);
                mma8(oacc[2*pp+1], pa0, pa1, pa2, pa3, vf[pp][1], vf[pp][3]);
            }
        }

        if (kt + 2 <= ktmax)      cp_wait<1>();
        else if (kt + 1 <= ktmax) cp_wait<0>();
    }

    lp0 += __shfl_xor_sync(0xffffffffu, lp0, 1);
    lp0 += __shfl_xor_sync(0xffffffffu, lp0, 2);
    lp1 += __shfl_xor_sync(0xffffffffu, lp1, 1);
    lp1 += __shfl_xor_sync(0xffffffffu, lp1, 2);
    const float i0 = 1.f / lp0, i1 = 1.f / lp1;
    {
        const int b = bh >> 4, h = bh & 15;
        const int r0 = qt * 128 + w * 16 + g;
        float* od = g_attn + (size_t)(b * SEQ + r0) * DM + h * 64;
        #pragma unroll
        for (int nt = 0; nt < 8; nt++){
            int c = nt * 8 + (j << 1);
            float4 a = oacc[nt];
            *(float2*)&od[c] =
                make_float2(tf32f(a.x * i0), tf32f(a.y * i0));
            *(float2*)&od[(size_t)8 * DM + c] =
                make_float2(tf32f(a.z * i1), tf32f(a.w * i1));
        }
    }
}

// ---------------------------------------------------------------------------
extern "C" void kernel_launch(void* const* d_in, const int* in_sizes, int n_in,
                              void* d_out, int out_size)
{
    const float* x     = (const float*)d_in[0];
    const float* w_qkv = (const float*)d_in[1];
    const float* b_qkv = (const float*)d_in[2];
    const float* w_out = (const float*)d_in[3];
    const float* b_out = (const float*)d_in[4];
    float* out = (float*)d_out;

    cudaFuncSetAttribute(gemm_tc, cudaFuncAttributeMaxDynamicSharedMemorySize, GSMEM_BYTES);
    cudaFuncSetAttribute(attn_tc, cudaFuncAttributeMaxDynamicSharedMemorySize, AT_SMEM_BYTES);

    round_x<<<(MR * DM / 4 + 255) / 256, 256>>>((const float4*)x, MR * DM / 4);
    transpose_w<<<dim3(128, 32), dim3(32, 8)>>>(w_qkv, w_out);

    gemm_tc<<<GRIDC, 256, GSMEM_BYTES>>>(b_qkv, nullptr, 0, 1536, 24);
    attn_tc<<<dim3(SEQ / 128, BH), 256, AT_SMEM_BYTES>>>();
    gemm_tc<<<GRIDC, 256, GSMEM_BYTES>>>(b_out, out, 1, 512, 8);
}